// round 3
// baseline (speedup 1.0000x reference)
#include <cuda_runtime.h>

// EffectiveProbability: post = normalize(p * (CM @ c)) per pixel.
// Input row-normalizations cancel against the output normalization -> skipped.
//
// prior/current [8,21,512,512] f32, cm [21,21] f32, out [B*H*W,21] f32.
//
// R3: LDS-floor attack. 2 pixels/thread via packed f32x2 math; CM staged in
// smem as duplicated pairs so one LDS.128 feeds 2 j-steps x 2 pixels
// (441 -> 231 LDS per pixel-pair, ~4x fewer per pixel than R1).
// fma.rn.f32x2 halves FFMA issue. Prior prefetched 1 iter ahead.

#define NCLS 21
#define NJ2  11                 // ceil(21/2) duplicated-pair columns
#define HWSHIFT 18              // H*W = 2^18
#define HWSZ (1 << HWSHIFT)
#define BLOCK 256
#define PIX_PER_BLOCK (2 * BLOCK)

typedef unsigned long long u64;

__device__ __forceinline__ u64 ffma2(u64 a, u64 b, u64 c) {
    u64 d; asm("fma.rn.f32x2 %0, %1, %2, %3;" : "=l"(d) : "l"(a), "l"(b), "l"(c));
    return d;
}
__device__ __forceinline__ u64 fmul2(u64 a, u64 b) {
    u64 d; asm("mul.rn.f32x2 %0, %1, %2;" : "=l"(d) : "l"(a), "l"(b));
    return d;
}
__device__ __forceinline__ u64 fadd2(u64 a, u64 b) {
    u64 d; asm("add.rn.f32x2 %0, %1, %2;" : "=l"(d) : "l"(a), "l"(b));
    return d;
}
__device__ __forceinline__ void unpack2(u64 v, float& lo, float& hi) {
    asm("mov.b64 {%0, %1}, %2;" : "=f"(lo), "=f"(hi) : "l"(v));
}
__device__ __forceinline__ u64 pack2(float lo, float hi) {
    u64 v; asm("mov.b64 %0, {%1, %2};" : "=l"(v) : "f"(lo), "f"(hi));
    return v;
}

__global__ __launch_bounds__(BLOCK, 4)
void eff_prob_kernel(const float* __restrict__ prior,
                     const float* __restrict__ current,
                     const float* __restrict__ cm,
                     float* __restrict__ out,
                     int npix)
{
    // CM as duplicated pairs: s_cm4[i*NJ2 + j2] = {(v2j,v2j), (v2j+1,v2j+1)}
    __shared__ ulonglong2 s_cm4[NCLS * NJ2];
    __shared__ float s_out[PIX_PER_BLOCK * NCLS];
    __shared__ float s_inv[PIX_PER_BLOCK];

    const int tid = threadIdx.x;

    for (int idx = tid; idx < NCLS * NJ2; idx += BLOCK) {
        const int i = idx / NJ2, j2 = idx - i * NJ2;
        const float v0 = cm[i * NCLS + 2 * j2];
        const float v1 = (2 * j2 + 1 < NCLS) ? cm[i * NCLS + 2 * j2 + 1] : 0.0f;
        s_cm4[idx] = make_ulonglong2(pack2(v0, v0), pack2(v1, v1));
    }
    __syncthreads();

    const int g2 = blockIdx.x * PIX_PER_BLOCK + 2 * tid;   // even pixel of this thread's pair
    if (g2 < npix) {
        const int b  = g2 >> HWSHIFT;
        const int hw = g2 & (HWSZ - 1);
        const size_t base = (size_t)b * (NCLS << HWSHIFT) + hw;   // 2-aligned element offset
        const u64* __restrict__ cp2 = (const u64*)(current + base);
        const u64* __restrict__ pp2 = (const u64*)(prior + base);

        // Front-batched coalesced LDG.64 of the current distribution (2 pixels).
        u64 cv[NCLS + 1];
        #pragma unroll
        for (int j = 0; j < NCLS; j++) cv[j] = cp2[(size_t)j << (HWSHIFT - 1)];
        cv[NCLS] = 0;   // zero pad for the duplicated-pair tail

        u64 pnext = pp2[0];
        u64 acc2  = 0;                              // packed (0.f, 0.f)
        float* so0 = s_out + tid * NCLS;                     // even pixel row
        float* so1 = s_out + (BLOCK + tid) * NCLS;           // odd pixel row

        #pragma unroll
        for (int i = 0; i < NCLS; i++) {
            u64 s2 = 0;
            #pragma unroll
            for (int j2 = 0; j2 < NJ2; j2++) {
                const ulonglong2 w = s_cm4[i * NJ2 + j2];    // LDS.128, broadcast
                s2 = ffma2(w.x, cv[2 * j2],     s2);
                s2 = ffma2(w.y, cv[2 * j2 + 1], s2);
            }
            const u64 pcur = pnext;
            if (i + 1 < NCLS) pnext = pp2[(size_t)(i + 1) << (HWSHIFT - 1)];
            const u64 t2 = fmul2(pcur, s2);
            float tlo, thi; unpack2(t2, tlo, thi);
            so0[i] = tlo;                                    // stride 21: conflict-free
            so1[i] = thi;
            acc2 = fadd2(acc2, t2);
        }
        float alo, ahi; unpack2(acc2, alo, ahi);
        s_inv[tid]         = 1.0f / alo;
        s_inv[BLOCK + tid] = 1.0f / ahi;
    }
    __syncthreads();

    // Flush [PIX_PER_BLOCK, 21] -> fully coalesced stores.
    // Output pixel p (block-local): p=2m -> smem row m; p=2m+1 -> row BLOCK+m.
    const long out_base = (long)blockIdx.x * PIX_PER_BLOCK * NCLS;
    const int  valid    = min(PIX_PER_BLOCK, npix - blockIdx.x * PIX_PER_BLOCK);
    const int  count    = valid * NCLS;
    for (int k = tid; k < count; k += BLOCK) {
        const int pix   = k / NCLS;                // magic-multiply, no real div
        const int c     = k - pix * NCLS;
        const int row   = ((pix & 1) ? BLOCK : 0) + (pix >> 1);
        out[out_base + k] = s_out[row * NCLS + c] * s_inv[row];
    }
}

extern "C" void kernel_launch(void* const* d_in, const int* in_sizes, int n_in,
                              void* d_out, int out_size)
{
    const float* prior   = (const float*)d_in[0];
    const float* current = (const float*)d_in[1];
    const float* cm      = (const float*)d_in[2];
    float*       out     = (float*)d_out;

    const int npix = in_sizes[0] / NCLS;   // B*H*W
    const int grid = (npix + PIX_PER_BLOCK - 1) / PIX_PER_BLOCK;
    eff_prob_kernel<<<grid, BLOCK>>>(prior, current, cm, out, npix);
}

// round 4
// speedup vs baseline: 1.2702x; 1.2702x over previous
#include <cuda_runtime.h>

// EffectiveProbability: post = normalize(p * (CM @ c)) per pixel.
// Input row-normalizations cancel against the output normalization -> skipped.
//
// prior/current [8,21,512,512] f32, cm [21,21] f32, out [B*H*W,21] f32.
//
// R4: R1 structure (best so far) + ONE change against the measured LDS floor:
// CM staged as float4 rows padded to 24 -> 6 LDS.128 (broadcast) per output
// class instead of 21 LDS.32 (441 -> 126 LDS/pixel). Normalization deferred
// to the flush (s_inv) to drop the post[21] register array while keeping
// both cv[] and pv[] front-batched (R2 showed in-loop prior loads kill MLP).

#define NCLS 21
#define NQ   6                  // ceil(21/4) float4 chunks per CM row
#define NPAD 24                 // padded row length
#define HWSHIFT 18              // H*W = 512*512 = 2^18
#define HWSZ (1 << HWSHIFT)
#define BLOCK 256

__global__ __launch_bounds__(BLOCK)
void eff_prob_kernel(const float* __restrict__ prior,
                     const float* __restrict__ current,
                     const float* __restrict__ cm,
                     float* __restrict__ out,
                     int npix)
{
    __shared__ float4 s_cm[NCLS * NQ];          // [21][6] float4, rows padded with 0
    __shared__ float  s_out[BLOCK * NCLS];
    __shared__ float  s_inv[BLOCK];

    const int tid = threadIdx.x;

    for (int idx = tid; idx < NCLS * NQ; idx += BLOCK) {
        const int i = idx / NQ, q = idx - i * NQ;
        float v[4];
        #pragma unroll
        for (int k = 0; k < 4; k++) {
            const int j = 4 * q + k;
            v[k] = (j < NCLS) ? cm[i * NCLS + j] : 0.0f;
        }
        s_cm[idx] = make_float4(v[0], v[1], v[2], v[3]);
    }
    __syncthreads();

    const int n = blockIdx.x * BLOCK + tid;
    if (n < npix) {
        const int b  = n >> HWSHIFT;
        const int hw = n & (HWSZ - 1);
        const size_t base = (size_t)b * (NCLS << HWSHIFT) + hw;
        const float* __restrict__ cp = current + base;
        const float* __restrict__ pp = prior + base;

        // Front-batched fully-coalesced loads: maximum MLP (R1's winning property).
        float cv[NPAD];
        #pragma unroll
        for (int j = 0; j < NCLS; j++) cv[j] = cp[(size_t)j << HWSHIFT];
        cv[21] = cv[22] = cv[23] = 0.0f;        // pad for float4 tail

        float pv[NCLS];
        #pragma unroll
        for (int j = 0; j < NCLS; j++) pv[j] = pp[(size_t)j << HWSHIFT];

        float acc = 0.0f;
        float* so = s_out + tid * NCLS;         // stride 21: gcd(21,32)=1, conflict-free
        #pragma unroll
        for (int i = 0; i < NCLS; i++) {
            float s = 0.0f;
            #pragma unroll
            for (int q = 0; q < NQ; q++) {
                const float4 w = s_cm[i * NQ + q];   // one LDS.128 broadcast
                s = fmaf(w.x, cv[4 * q + 0], s);
                s = fmaf(w.y, cv[4 * q + 1], s);
                s = fmaf(w.z, cv[4 * q + 2], s);
                s = fmaf(w.w, cv[4 * q + 3], s);
            }
            const float t = pv[i] * s;
            so[i] = t;
            acc += t;
        }
        s_inv[tid] = 1.0f / acc;
    }
    __syncthreads();

    // Flush block tile [BLOCK, 21] linearly: fully coalesced 128B stores.
    const long out_base = (long)blockIdx.x * BLOCK * NCLS;
    const int  valid    = min(BLOCK, npix - blockIdx.x * BLOCK);
    const int  count    = valid * NCLS;
    for (int k = tid; k < count; k += BLOCK)
        out[out_base + k] = s_out[k] * s_inv[k / NCLS];   // const-div -> magic mul
}

extern "C" void kernel_launch(void* const* d_in, const int* in_sizes, int n_in,
                              void* d_out, int out_size)
{
    const float* prior   = (const float*)d_in[0];
    const float* current = (const float*)d_in[1];
    const float* cm      = (const float*)d_in[2];
    float*       out     = (float*)d_out;

    const int npix = in_sizes[0] / NCLS;   // B*H*W
    const int grid = (npix + BLOCK - 1) / BLOCK;
    eff_prob_kernel<<<grid, BLOCK>>>(prior, current, cm, out, npix);
}

// round 5
// speedup vs baseline: 1.2985x; 1.0223x over previous
#include <cuda_runtime.h>

// EffectiveProbability: post = normalize(p * (CM @ c)) per pixel.
// Input row-normalizations cancel against the output normalization -> skipped.
//
// prior/current [8,21,512,512] f32, cm [21,21] f32, out [B*H*W,21] f32.
//
// R5: attack the measured LDS-broadcast floor (441 wf/pixel ~= 105us in R1).
// 2 pixels per thread with two scalar FFMA chains sharing each LDS.32
// broadcast of cm[i][j] -> 220 LDS wf/pixel (~52us), overlapping the FFMA
// issue floor (~52us). Scalar LDS only (LDS.128 measured as 4 non-deduped
// wavefronts in R4). cv front-batched for both pixels (42 coalesced LDG,
// < M_max=55); prior via depth-2 prefetch ring. Pixel pair (tid, tid+256)
// keeps STS stride-21 conflict-free and smem rows in output order.

#define NCLS 21
#define HWSHIFT 18              // H*W = 512*512 = 2^18
#define HWSZ (1 << HWSHIFT)
#define BLOCK 256
#define PPB (2 * BLOCK)         // pixels per block

__device__ __forceinline__ void process_one_pixel(
    const float* __restrict__ prior, const float* __restrict__ current,
    const float* __restrict__ s_cm, float* __restrict__ so, float* inv_slot,
    int n)
{
    const int b  = n >> HWSHIFT;
    const int hw = n & (HWSZ - 1);
    const size_t base = ((size_t)b * NCLS << HWSHIFT) + hw;
    const float* __restrict__ cp = current + base;
    const float* __restrict__ pp = prior + base;

    float cv[NCLS];
    #pragma unroll
    for (int j = 0; j < NCLS; j++) cv[j] = cp[(size_t)j << HWSHIFT];
    float pv[NCLS];
    #pragma unroll
    for (int j = 0; j < NCLS; j++) pv[j] = pp[(size_t)j << HWSHIFT];

    float acc = 0.0f;
    #pragma unroll
    for (int i = 0; i < NCLS; i++) {
        float s = 0.0f;
        #pragma unroll
        for (int j = 0; j < NCLS; j++) s = fmaf(s_cm[i * NCLS + j], cv[j], s);
        const float t = pv[i] * s;
        so[i] = t;
        acc += t;
    }
    *inv_slot = 1.0f / acc;
}

__global__ __launch_bounds__(BLOCK)
void eff_prob_kernel(const float* __restrict__ prior,
                     const float* __restrict__ current,
                     const float* __restrict__ cm,
                     float* __restrict__ out,
                     int npix)
{
    __shared__ float s_cm[NCLS * NCLS];
    __shared__ float s_out[PPB * NCLS];      // 43008 B
    __shared__ float s_inv[PPB];             // total ~46.8 KB static

    const int tid = threadIdx.x;
    for (int i = tid; i < NCLS * NCLS; i += BLOCK) s_cm[i] = cm[i];
    __syncthreads();

    const int blk_base = blockIdx.x * PPB;
    const int pA = blk_base + tid;           // smem row tid
    const int pB = pA + BLOCK;                // smem row BLOCK+tid

    if (pB < npix) {
        // ---- main dual-pixel path ----
        const int bA = pA >> HWSHIFT, hwA = pA & (HWSZ - 1);
        const int bB = pB >> HWSHIFT, hwB = pB & (HWSZ - 1);
        const size_t baseA = ((size_t)bA * NCLS << HWSHIFT) + hwA;
        const size_t baseB = ((size_t)bB * NCLS << HWSHIFT) + hwB;
        const float* __restrict__ cpA = current + baseA;
        const float* __restrict__ cpB = current + baseB;
        const float* __restrict__ ppA = prior + baseA;
        const float* __restrict__ ppB = prior + baseB;

        // Front-batched coalesced loads: 42 independent LDG.32 (max MLP).
        float cvA[NCLS], cvB[NCLS];
        #pragma unroll
        for (int j = 0; j < NCLS; j++) cvA[j] = cpA[(size_t)j << HWSHIFT];
        #pragma unroll
        for (int j = 0; j < NCLS; j++) cvB[j] = cpB[(size_t)j << HWSHIFT];

        // Prior prefetch ring, depth 2.
        float pA0 = ppA[0], pB0 = ppB[0];
        float pA1 = ppA[(size_t)1 << HWSHIFT], pB1 = ppB[(size_t)1 << HWSHIFT];

        float accA = 0.0f, accB = 0.0f;
        float* soA = s_out + tid * NCLS;              // stride 21: conflict-free
        float* soB = s_out + (BLOCK + tid) * NCLS;

        #pragma unroll
        for (int i = 0; i < NCLS; i++) {
            const float pa = pA0, pb = pB0;
            pA0 = pA1; pB0 = pB1;
            if (i + 2 < NCLS) {
                pA1 = ppA[(size_t)(i + 2) << HWSHIFT];
                pB1 = ppB[(size_t)(i + 2) << HWSHIFT];
            }
            float sA = 0.0f, sB = 0.0f;
            #pragma unroll
            for (int j = 0; j < NCLS; j++) {
                const float w = s_cm[i * NCLS + j];   // one LDS.32 broadcast, 2 FFMAs
                sA = fmaf(w, cvA[j], sA);
                sB = fmaf(w, cvB[j], sB);
            }
            const float tA = pa * sA;
            const float tB = pb * sB;
            soA[i] = tA;
            soB[i] = tB;
            accA += tA;
            accB += tB;
        }
        s_inv[tid]         = 1.0f / accA;
        s_inv[BLOCK + tid] = 1.0f / accB;
    } else {
        // ---- tail: at most one valid pixel per thread ----
        if (pA < npix)
            process_one_pixel(prior, current, s_cm,
                              s_out + tid * NCLS, &s_inv[tid], pA);
    }
    __syncthreads();

    // Flush [PPB, 21] tile linearly: fully coalesced 128B stores.
    const long out_base = (long)blk_base * NCLS;
    const int  valid    = min(PPB, npix - blk_base);
    const int  count    = valid * NCLS;
    for (int k = tid; k < count; k += BLOCK)
        out[out_base + k] = s_out[k] * s_inv[k / NCLS];   // const-div -> magic mul
}

extern "C" void kernel_launch(void* const* d_in, const int* in_sizes, int n_in,
                              void* d_out, int out_size)
{
    const float* prior   = (const float*)d_in[0];
    const float* current = (const float*)d_in[1];
    const float* cm      = (const float*)d_in[2];
    float*       out     = (float*)d_out;

    const int npix = in_sizes[0] / NCLS;   // B*H*W
    const int grid = (npix + PPB - 1) / PPB;
    eff_prob_kernel<<<grid, BLOCK>>>(prior, current, cm, out, npix);
}